// round 1
// baseline (speedup 1.0000x reference)
#include <cuda_runtime.h>

#define NN 10000
#define NE 320000
#define FD 64
#define HD 256
#define GD 256
#define H3 768

// ---------------- static scratch (no allocs allowed) ----------------
__device__ float d_XG[NN * H3];      // x_t @ W_ih^T + b_ih
__device__ float d_GH[NN * H3];      // h   @ W_hh^T + b_hh
__device__ float d_COMB[NN * H3];    // [hs|hm|hl]
__device__ float d_HS[NN * HD];
__device__ float d_HM[NN * HD];
__device__ float d_HL[NN * HD];
__device__ float d_TEMB[NN * GD];
__device__ float d_XL[NN * GD];
__device__ float d_AGG[NN * GD];
__device__ float d_G1[NN * GD];
__device__ float d_G2[NN * GD];
__device__ float d_P[NN];
__device__ float d_Q[NN];
__device__ float d_SSUM[NN];
__device__ unsigned d_MENC[NN];
__device__ float d_SC[NE];

// ---------------- packed f32x2 helpers (sm_103a) ----------------
__device__ __forceinline__ unsigned long long pack2(float x, float y) {
    unsigned long long r;
    asm("mov.b64 %0, {%1, %2};" : "=l"(r) : "f"(x), "f"(y));
    return r;
}
__device__ __forceinline__ void unpack2(unsigned long long v, float& x, float& y) {
    asm("mov.b64 {%0, %1}, %2;" : "=f"(x), "=f"(y) : "l"(v));
}
__device__ __forceinline__ void ffma2(unsigned long long& d, unsigned long long a,
                                      unsigned long long b) {
    asm("fma.rn.f32x2 %0, %1, %2, %0;" : "+l"(d) : "l"(a), "l"(b));
}

// ---------------- GEMM: C[M,N] = A[M,K] * B[N,K]^T + bias (opt relu) -------
// BM=128, BN=64, BK=16, 256 threads, 8x4 per thread, f32x2 inner product.
__global__ void __launch_bounds__(256) gemm_tn(
    const float* __restrict__ A, int lda,
    const float* __restrict__ B, int ldb,
    const float* __restrict__ bias,
    float* __restrict__ C, int ldc,
    int M, int K, int relu)
{
    __shared__ float As[16][128];
    __shared__ float Bs[16][64];
    const int tid = threadIdx.x;
    const int m0 = blockIdx.x * 128;
    const int n0 = blockIdx.y * 64;
    const int tx = tid & 15;
    const int ty = tid >> 4;

    unsigned long long acc[8][2];
#pragma unroll
    for (int i = 0; i < 8; i++) { acc[i][0] = 0ull; acc[i][1] = 0ull; }

    const int ar0 = tid >> 2;
    const int ar1 = (tid + 256) >> 2;
    const int aq = tid & 3;
    const int br = tid >> 2;
    const int bq = tid & 3;

    for (int k0 = 0; k0 < K; k0 += 16) {
        float4 va0 = make_float4(0.f, 0.f, 0.f, 0.f);
        float4 va1 = va0;
        if (m0 + ar0 < M) va0 = *(const float4*)(A + (size_t)(m0 + ar0) * lda + k0 + aq * 4);
        if (m0 + ar1 < M) va1 = *(const float4*)(A + (size_t)(m0 + ar1) * lda + k0 + aq * 4);
        float4 vb = *(const float4*)(B + (size_t)(n0 + br) * ldb + k0 + bq * 4);

        As[aq * 4 + 0][ar0] = va0.x; As[aq * 4 + 1][ar0] = va0.y;
        As[aq * 4 + 2][ar0] = va0.z; As[aq * 4 + 3][ar0] = va0.w;
        As[aq * 4 + 0][ar1] = va1.x; As[aq * 4 + 1][ar1] = va1.y;
        As[aq * 4 + 2][ar1] = va1.z; As[aq * 4 + 3][ar1] = va1.w;
        Bs[bq * 4 + 0][br] = vb.x; Bs[bq * 4 + 1][br] = vb.y;
        Bs[bq * 4 + 2][br] = vb.z; Bs[bq * 4 + 3][br] = vb.w;
        __syncthreads();

#pragma unroll
        for (int kk = 0; kk < 16; kk++) {
            float4 a0 = *(const float4*)&As[kk][ty * 8];
            float4 a1 = *(const float4*)&As[kk][ty * 8 + 4];
            unsigned long long b0 = *(const unsigned long long*)&Bs[kk][tx * 4];
            unsigned long long b1 = *(const unsigned long long*)&Bs[kk][tx * 4 + 2];
            float av[8] = {a0.x, a0.y, a0.z, a0.w, a1.x, a1.y, a1.z, a1.w};
#pragma unroll
            for (int i = 0; i < 8; i++) {
                unsigned long long a2 = pack2(av[i], av[i]);
                ffma2(acc[i][0], a2, b0);
                ffma2(acc[i][1], a2, b1);
            }
        }
        __syncthreads();
    }

    float b4[4] = {0.f, 0.f, 0.f, 0.f};
    if (bias) {
        float4 bv = *(const float4*)(bias + n0 + tx * 4);
        b4[0] = bv.x; b4[1] = bv.y; b4[2] = bv.z; b4[3] = bv.w;
    }
#pragma unroll
    for (int i = 0; i < 8; i++) {
        int m = m0 + ty * 8 + i;
        if (m < M) {
            float c0, c1, c2, c3;
            unpack2(acc[i][0], c0, c1);
            unpack2(acc[i][1], c2, c3);
            c0 += b4[0]; c1 += b4[1]; c2 += b4[2]; c3 += b4[3];
            if (relu) {
                c0 = fmaxf(c0, 0.f); c1 = fmaxf(c1, 0.f);
                c2 = fmaxf(c2, 0.f); c3 = fmaxf(c3, 0.f);
            }
            *(float4*)(C + (size_t)m * ldc + n0 + tx * 4) = make_float4(c0, c1, c2, c3);
        }
    }
}

// ---------------- GRU gate update ----------------
__global__ void gru_gate(float* __restrict__ h) {
    int n = blockIdx.x;
    int j = threadIdx.x;
    const float* xg = d_XG + (size_t)n * H3;
    const float* gh = d_GH + (size_t)n * H3;
    float r = 1.f / (1.f + expf(-(xg[j] + gh[j])));
    float z = 1.f / (1.f + expf(-(xg[j + 256] + gh[j + 256])));
    float nn = tanhf(xg[j + 512] + r * gh[j + 512]);
    float ho = h[(size_t)n * HD + j];
    h[(size_t)n * HD + j] = (1.f - z) * nn + z * ho;
}

__global__ void k_concat() {
    int i = blockIdx.x * 256 + threadIdx.x;
    if (i >= NN * H3) return;
    int n = i / H3, j = i % H3;
    float v;
    if (j < 256)      v = d_HS[n * HD + j];
    else if (j < 512) v = d_HM[n * HD + j - 256];
    else              v = d_HL[n * HD + j - 512];
    d_COMB[i] = v;
}

// ---------------- SAGE attention (decomposed scores) ----------------
__device__ __forceinline__ unsigned fenc(float f) {
    unsigned u = __float_as_uint(f);
    return (u & 0x80000000u) ? ~u : (u | 0x80000000u);
}
__device__ __forceinline__ float fdec(unsigned u) {
    u = (u & 0x80000000u) ? (u & 0x7fffffffu) : ~u;
    return __uint_as_float(u);
}

__global__ void k_pq(const float* __restrict__ aw) {
    int n = blockIdx.x * 8 + (threadIdx.x >> 5);
    int lane = threadIdx.x & 31;
    if (n >= NN) return;
    float p = 0.f, q = 0.f;
#pragma unroll
    for (int j = lane; j < 256; j += 32) {
        float v = d_XL[n * GD + j];
        p += v * aw[j];
        q += v * aw[256 + j];
    }
#pragma unroll
    for (int o = 16; o; o >>= 1) {
        p += __shfl_xor_sync(0xffffffffu, p, o);
        q += __shfl_xor_sync(0xffffffffu, q, o);
    }
    if (lane == 0) { d_P[n] = p; d_Q[n] = q; }
}

__global__ void k_init() {
    int n = blockIdx.x * 256 + threadIdx.x;
    if (n < NN) { d_MENC[n] = 0x007fffffu; d_SSUM[n] = 0.f; }  // fenc(-inf)
}

__global__ void k_edge1(const int* __restrict__ ei, const float* __restrict__ ea,
                        const float* __restrict__ aw, const float* __restrict__ ab) {
    int e = blockIdx.x * 256 + threadIdx.x;
    if (e >= NE) return;
    int row = ei[e], col = ei[NE + e];
    float sc = d_P[row] + d_Q[col] + aw[512] * ea[e] + ab[0];
    d_SC[e] = sc;
    atomicMax(&d_MENC[row], fenc(sc));
}

__global__ void k_edge2(const int* __restrict__ ei) {
    int e = blockIdx.x * 256 + threadIdx.x;
    if (e >= NE) return;
    int row = ei[e];
    float m = fdec(d_MENC[row]);
    float ex = expf(d_SC[e] - m);
    d_SC[e] = ex;
    atomicAdd(&d_SSUM[row], ex);
}

__global__ void k_edge3(const int* __restrict__ ei) {
    int e = blockIdx.x * 4 + (threadIdx.x >> 6);
    int l = threadIdx.x & 63;
    if (e >= NE) return;
    int row = ei[e], col = ei[NE + e];
    float alpha = d_SC[e] / (d_SSUM[row] + 1e-16f);
    float4 v = *(const float4*)&d_XL[row * GD + l * 4];
    float* dst = &d_AGG[col * GD + l * 4];
    atomicAdd(dst + 0, alpha * v.x);
    atomicAdd(dst + 1, alpha * v.y);
    atomicAdd(dst + 2, alpha * v.z);
    atomicAdd(dst + 3, alpha * v.w);
}

__global__ void k_finish(const float* __restrict__ addsrc, float* __restrict__ dst) {
    int i = blockIdx.x * 256 + threadIdx.x;
    if (i >= NN * GD) return;
    float v = d_AGG[i];
    v = v > 0.f ? v : 0.f;
    if (addsrc) v += addsrc[i];
    dst[i] = v;
}

__global__ void k_heads(const float* __restrict__ impW, const float* __restrict__ impb,
                        const float* __restrict__ uncW, const float* __restrict__ uncb,
                        float* __restrict__ out) {
    int n = blockIdx.x * 8 + (threadIdx.x >> 5);
    int lane = threadIdx.x & 31;
    if (n >= NN) return;
    float a = 0.f, b = 0.f;
#pragma unroll
    for (int j = lane; j < GD; j += 32) {
        float v = d_G2[n * GD + j];
        a += v * impW[j];
        b += v * uncW[j];
    }
#pragma unroll
    for (int o = 16; o; o >>= 1) {
        a += __shfl_xor_sync(0xffffffffu, a, o);
        b += __shfl_xor_sync(0xffffffffu, b, o);
    }
    if (lane == 0) {
        out[n] = tanhf(a + impb[0]);
        out[NN + n] = 1.f / (1.f + expf(-(b + uncb[0])));
    }
}

// ---------------- host orchestration ----------------
extern "C" void kernel_launch(void* const* d_in, const int* in_sizes, int n_in,
                              void* d_out, int out_size)
{
    const float* x_s = (const float*)d_in[0];
    const float* x_m = (const float*)d_in[1];
    const float* x_l = (const float*)d_in[2];
    const int*   ei  = (const int*)d_in[3];
    const float* ea  = (const float*)d_in[4];
    const float* Wih[3] = {(const float*)d_in[5], (const float*)d_in[9],  (const float*)d_in[13]};
    const float* Whh[3] = {(const float*)d_in[6], (const float*)d_in[10], (const float*)d_in[14]};
    const float* bih[3] = {(const float*)d_in[7], (const float*)d_in[11], (const float*)d_in[15]};
    const float* bhh[3] = {(const float*)d_in[8], (const float*)d_in[12], (const float*)d_in[16]};
    const float* fW   = (const float*)d_in[17];
    const float* fb   = (const float*)d_in[18];
    const float* g1W  = (const float*)d_in[19];
    const float* g1aw = (const float*)d_in[20];
    const float* g1ab = (const float*)d_in[21];
    const float* g2W  = (const float*)d_in[22];
    const float* g2aw = (const float*)d_in[23];
    const float* g2ab = (const float*)d_in[24];
    const float* impW = (const float*)d_in[25];
    const float* impb = (const float*)d_in[26];
    const float* uncW = (const float*)d_in[27];
    const float* uncb = (const float*)d_in[28];

    void *pXG, *pGH, *pCOMB, *pHS, *pHM, *pHL, *pTEMB, *pXL, *pAGG, *pG1, *pG2;
    cudaGetSymbolAddress(&pXG, d_XG);
    cudaGetSymbolAddress(&pGH, d_GH);
    cudaGetSymbolAddress(&pCOMB, d_COMB);
    cudaGetSymbolAddress(&pHS, d_HS);
    cudaGetSymbolAddress(&pHM, d_HM);
    cudaGetSymbolAddress(&pHL, d_HL);
    cudaGetSymbolAddress(&pTEMB, d_TEMB);
    cudaGetSymbolAddress(&pXL, d_XL);
    cudaGetSymbolAddress(&pAGG, d_AGG);
    cudaGetSymbolAddress(&pG1, d_G1);
    cudaGetSymbolAddress(&pG2, d_G2);
    float* XG = (float*)pXG;   float* GH = (float*)pGH;
    float* COMB = (float*)pCOMB;
    float* HS = (float*)pHS;   float* HM = (float*)pHM;   float* HL = (float*)pHL;
    float* TEMB = (float*)pTEMB; float* XL = (float*)pXL; float* AGG = (float*)pAGG;
    float* G1 = (float*)pG1;   float* G2 = (float*)pG2;

    const float* xs[3] = {x_s, x_m, x_l};
    const int Ts[3] = {8, 30, 60};
    float* hb[3] = {HS, HM, HL};

    dim3 gB((NN + 127) / 128, H3 / 64);  // 79 x 12
    dim3 gS((NN + 127) / 128, GD / 64);  // 79 x 4

    // ---- three GRUs ----
    for (int s = 0; s < 3; s++) {
        cudaMemsetAsync(hb[s], 0, (size_t)NN * HD * sizeof(float));
        for (int t = 0; t < Ts[s]; t++) {
            gemm_tn<<<gB, 256>>>(xs[s] + t * FD, Ts[s] * FD, Wih[s], FD, bih[s],
                                 XG, H3, NN, FD, 0);
            gemm_tn<<<gB, 256>>>(hb[s], HD, Whh[s], HD, bhh[s],
                                 GH, H3, NN, HD, 0);
            gru_gate<<<NN, 256>>>(hb[s]);
        }
    }

    // ---- fusion ----
    k_concat<<<(NN * H3 + 255) / 256, 256>>>();
    gemm_tn<<<gS, 256>>>(COMB, H3, fW, H3, fb, TEMB, GD, NN, H3, 1);

    // ---- SAGE layer 1 ----
    gemm_tn<<<gS, 256>>>(TEMB, GD, g1W, GD, nullptr, XL, GD, NN, GD, 0);
    k_pq<<<(NN + 7) / 8, 256>>>(g1aw);
    k_init<<<(NN + 255) / 256, 256>>>();
    cudaMemsetAsync(AGG, 0, (size_t)NN * GD * sizeof(float));
    k_edge1<<<(NE + 255) / 256, 256>>>(ei, ea, g1aw, g1ab);
    k_edge2<<<(NE + 255) / 256, 256>>>(ei);
    k_edge3<<<NE / 4, 256>>>(ei);
    k_finish<<<(NN * GD + 255) / 256, 256>>>(nullptr, G1);

    // ---- SAGE layer 2 ----
    gemm_tn<<<gS, 256>>>(G1, GD, g2W, GD, nullptr, XL, GD, NN, GD, 0);
    k_pq<<<(NN + 7) / 8, 256>>>(g2aw);
    k_init<<<(NN + 255) / 256, 256>>>();
    cudaMemsetAsync(AGG, 0, (size_t)NN * GD * sizeof(float));
    k_edge1<<<(NE + 255) / 256, 256>>>(ei, ea, g2aw, g2ab);
    k_edge2<<<(NE + 255) / 256, 256>>>(ei);
    k_edge3<<<NE / 4, 256>>>(ei);
    k_finish<<<(NN * GD + 255) / 256, 256>>>(TEMB, G2);

    // ---- heads ----
    k_heads<<<(NN + 7) / 8, 256>>>(impW, impb, uncW, uncb, (float*)d_out);
}

// round 2
// speedup vs baseline: 1.8001x; 1.8001x over previous
#include <cuda_runtime.h>

#define NN 10000
#define NE 320000
#define FD 64
#define HD 256
#define GD 256
#define H3 768

// ---------------- static scratch (no allocs allowed) ----------------
__device__ float d_COMB[NN * H3];    // [hs|hm|hl]
__device__ float d_HS[NN * HD];
__device__ float d_HM[NN * HD];
__device__ float d_HL[NN * HD];
__device__ float d_HT[NN * HD];      // ping-pong partner
__device__ float d_TEMB[NN * GD];
__device__ float d_XL[NN * GD];
__device__ float d_AGG[NN * GD];
__device__ float d_G1[NN * GD];
__device__ float d_G2[NN * GD];
__device__ float d_P[NN];
__device__ float d_Q[NN];
__device__ float d_SSUM[NN];
__device__ unsigned d_MENC[NN];
__device__ float d_SC[NE];

// ================== fused GRU step: tf32 tensor-core ==================
// Computes, for all nodes:  gates = [x_t | h] @ [W_ih | W_hh]^T  (K=320)
// with 4 output chunks per hidden column j: r(K=320), z(K=320),
// i_n(K=64, x only), h_n(K=256, h only), then applies the GRU gate update
// in the epilogue. One kernel per timestep.
//
// Block: 512 thr (16 warps, 4m x 4n). Block tile M=128, N=256 (=64 j x 4 chunks).
// Warp tile 32x64 -> 2 m16 tiles x 8 n8 tiles. K-chunks of 32 (10 chunks).

__device__ __forceinline__ unsigned f2tf(float f) {
    unsigned r;
    asm("cvt.rna.tf32.f32 %0, %1;" : "=r"(r) : "f"(f));
    return r;
}
__device__ __forceinline__ float sigf(float x) { return 1.f / (1.f + expf(-x)); }

#define SM_A_ROWS 128
#define SM_B_ROWS 256
#define SM_PAD 36
#define FUSED_SMEM ((SM_A_ROWS + SM_B_ROWS) * SM_PAD * 4)

__global__ void __launch_bounds__(512) fused_gru_step(
    const float* __restrict__ x, int xstride,   // x already offset by t*FD
    const float* __restrict__ hprev,
    float* __restrict__ hnext,
    const float* __restrict__ Wih,   // [768][64]
    const float* __restrict__ Whh,   // [768][256]
    const float* __restrict__ bih,
    const float* __restrict__ bhh)
{
    extern __shared__ unsigned smem_u[];
    unsigned* As = smem_u;                       // [128][36]
    unsigned* Bs = smem_u + SM_A_ROWS * SM_PAD;  // [256][36]

    const int tid = threadIdx.x;
    const int m0 = blockIdx.x * 128;
    const int j0 = blockIdx.y * 64;
    const int lane = tid & 31;
    const int gid = lane >> 2, tig = lane & 3;
    const int warp = tid >> 5;
    const int wm = warp & 3, wn = warp >> 2;

    float acc[2][8][4];
#pragma unroll
    for (int i = 0; i < 2; i++)
#pragma unroll
        for (int j = 0; j < 8; j++)
#pragma unroll
            for (int r = 0; r < 4; r++) acc[i][j][r] = 0.f;

    const int lr = tid >> 3;         // 0..63
    const int lk = (tid & 7) * 4;    // 0..28

    for (int kb = 0; kb < 10; kb++) {
        // ---- load A tile (128 x 32): rows = nodes, cols = k
#pragma unroll
        for (int p = 0; p < 2; p++) {
            int r = lr + p * 64;
            int rg = m0 + r;
            float4 v = make_float4(0.f, 0.f, 0.f, 0.f);
            if (rg < NN) {
                if (kb < 2) v = *(const float4*)(x + (size_t)rg * xstride + kb * 32 + lk);
                else        v = *(const float4*)(hprev + (size_t)rg * HD + kb * 32 - 64 + lk);
            }
            unsigned* d = As + r * SM_PAD + lk;
            d[0] = f2tf(v.x); d[1] = f2tf(v.y); d[2] = f2tf(v.z); d[3] = f2tf(v.w);
        }
        // ---- load B tile (256 x 32): row q -> (chunk c, col j)
#pragma unroll
        for (int p = 0; p < 4; p++) {
            int q = lr + p * 64;
            int c = (q >> 3) & 3;
            int j = (q >> 5) * 8 + (q & 7);
            int wrow = (c < 2 ? c * 256 : 512) + j0 + j;
            float4 v = make_float4(0.f, 0.f, 0.f, 0.f);
            bool zero = (c == 2 && kb >= 2) || (c == 3 && kb < 2);
            if (!zero) {
                if (kb < 2) v = *(const float4*)(Wih + (size_t)wrow * FD + kb * 32 + lk);
                else        v = *(const float4*)(Whh + (size_t)wrow * HD + kb * 32 - 64 + lk);
            }
            unsigned* d = Bs + q * SM_PAD + lk;
            d[0] = f2tf(v.x); d[1] = f2tf(v.y); d[2] = f2tf(v.z); d[3] = f2tf(v.w);
        }
        __syncthreads();

        // ---- compute: 4 k-steps of 8
#pragma unroll
        for (int ks = 0; ks < 4; ks++) {
            const int kk = ks * 8;
            unsigned af[2][4];
#pragma unroll
            for (int i = 0; i < 2; i++) {
                int rb = (wm * 32 + i * 16 + gid) * SM_PAD;
                af[i][0] = As[rb + kk + tig];
                af[i][1] = As[rb + 8 * SM_PAD + kk + tig];
                af[i][2] = As[rb + kk + tig + 4];
                af[i][3] = As[rb + 8 * SM_PAD + kk + tig + 4];
            }
            unsigned bf[8][2];
#pragma unroll
            for (int jt = 0; jt < 8; jt++) {
                int qb = (wn * 64 + jt * 8 + gid) * SM_PAD;
                bf[jt][0] = Bs[qb + kk + tig];
                bf[jt][1] = Bs[qb + kk + tig + 4];
            }
#pragma unroll
            for (int i = 0; i < 2; i++)
#pragma unroll
                for (int jt = 0; jt < 8; jt++) {
                    asm volatile(
                        "mma.sync.aligned.m16n8k8.row.col.f32.tf32.tf32.f32 "
                        "{%0,%1,%2,%3},{%4,%5,%6,%7},{%8,%9},{%0,%1,%2,%3};"
                        : "+f"(acc[i][jt][0]), "+f"(acc[i][jt][1]),
                          "+f"(acc[i][jt][2]), "+f"(acc[i][jt][3])
                        : "r"(af[i][0]), "r"(af[i][1]), "r"(af[i][2]), "r"(af[i][3]),
                          "r"(bf[jt][0]), "r"(bf[jt][1]));
                }
        }
        __syncthreads();
    }

    // ---- epilogue: GRU gate update
#pragma unroll
    for (int i = 0; i < 2; i++)
#pragma unroll
        for (int h = 0; h < 2; h++)
#pragma unroll
            for (int gl = 0; gl < 2; gl++)
#pragma unroll
                for (int pp = 0; pp < 2; pp++) {
                    int reg = h * 2 + pp;
                    float ar = acc[i][gl * 4 + 0][reg];
                    float az = acc[i][gl * 4 + 1][reg];
                    float ain = acc[i][gl * 4 + 2][reg];
                    float ahn = acc[i][gl * 4 + 3][reg];
                    int row = m0 + wm * 32 + i * 16 + gid + h * 8;
                    int j = (wn * 2 + gl) * 8 + 2 * tig + pp + j0;
                    if (row < NN) {
                        float r = sigf(ar + bih[j] + bhh[j]);
                        float z = sigf(az + bih[256 + j] + bhh[256 + j]);
                        float n = tanhf(ain + bih[512 + j] + r * (ahn + bhh[512 + j]));
                        float ho = hprev[(size_t)row * HD + j];
                        hnext[(size_t)row * HD + j] = (1.f - z) * n + z * ho;
                    }
                }
}

// ---------------- packed f32x2 helpers (sm_103a) ----------------
__device__ __forceinline__ unsigned long long pack2(float x, float y) {
    unsigned long long r;
    asm("mov.b64 %0, {%1, %2};" : "=l"(r) : "f"(x), "f"(y));
    return r;
}
__device__ __forceinline__ void unpack2(unsigned long long v, float& x, float& y) {
    asm("mov.b64 {%0, %1}, %2;" : "=f"(x), "=f"(y) : "l"(v));
}
__device__ __forceinline__ void ffma2(unsigned long long& d, unsigned long long a,
                                      unsigned long long b) {
    asm("fma.rn.f32x2 %0, %1, %2, %0;" : "+l"(d) : "l"(a), "l"(b));
}

// ---------------- GEMM: C[M,N] = A[M,K] * B[N,K]^T + bias (opt relu) -------
__global__ void __launch_bounds__(256) gemm_tn(
    const float* __restrict__ A, int lda,
    const float* __restrict__ B, int ldb,
    const float* __restrict__ bias,
    float* __restrict__ C, int ldc,
    int M, int K, int relu)
{
    __shared__ float As[16][128];
    __shared__ float Bs[16][64];
    const int tid = threadIdx.x;
    const int m0 = blockIdx.x * 128;
    const int n0 = blockIdx.y * 64;
    const int tx = tid & 15;
    const int ty = tid >> 4;

    unsigned long long acc[8][2];
#pragma unroll
    for (int i = 0; i < 8; i++) { acc[i][0] = 0ull; acc[i][1] = 0ull; }

    const int ar0 = tid >> 2;
    const int ar1 = (tid + 256) >> 2;
    const int aq = tid & 3;
    const int br = tid >> 2;
    const int bq = tid & 3;

    for (int k0 = 0; k0 < K; k0 += 16) {
        float4 va0 = make_float4(0.f, 0.f, 0.f, 0.f);
        float4 va1 = va0;
        if (m0 + ar0 < M) va0 = *(const float4*)(A + (size_t)(m0 + ar0) * lda + k0 + aq * 4);
        if (m0 + ar1 < M) va1 = *(const float4*)(A + (size_t)(m0 + ar1) * lda + k0 + aq * 4);
        float4 vb = *(const float4*)(B + (size_t)(n0 + br) * ldb + k0 + bq * 4);

        As[aq * 4 + 0][ar0] = va0.x; As[aq * 4 + 1][ar0] = va0.y;
        As[aq * 4 + 2][ar0] = va0.z; As[aq * 4 + 3][ar0] = va0.w;
        As[aq * 4 + 0][ar1] = va1.x; As[aq * 4 + 1][ar1] = va1.y;
        As[aq * 4 + 2][ar1] = va1.z; As[aq * 4 + 3][ar1] = va1.w;
        Bs[bq * 4 + 0][br] = vb.x; Bs[bq * 4 + 1][br] = vb.y;
        Bs[bq * 4 + 2][br] = vb.z; Bs[bq * 4 + 3][br] = vb.w;
        __syncthreads();

#pragma unroll
        for (int kk = 0; kk < 16; kk++) {
            float4 a0 = *(const float4*)&As[kk][ty * 8];
            float4 a1 = *(const float4*)&As[kk][ty * 8 + 4];
            unsigned long long b0 = *(const unsigned long long*)&Bs[kk][tx * 4];
            unsigned long long b1 = *(const unsigned long long*)&Bs[kk][tx * 4 + 2];
            float av[8] = {a0.x, a0.y, a0.z, a0.w, a1.x, a1.y, a1.z, a1.w};
#pragma unroll
            for (int i = 0; i < 8; i++) {
                unsigned long long a2 = pack2(av[i], av[i]);
                ffma2(acc[i][0], a2, b0);
                ffma2(acc[i][1], a2, b1);
            }
        }
        __syncthreads();
    }

    float b4[4] = {0.f, 0.f, 0.f, 0.f};
    if (bias) {
        float4 bv = *(const float4*)(bias + n0 + tx * 4);
        b4[0] = bv.x; b4[1] = bv.y; b4[2] = bv.z; b4[3] = bv.w;
    }
#pragma unroll
    for (int i = 0; i < 8; i++) {
        int m = m0 + ty * 8 + i;
        if (m < M) {
            float c0, c1, c2, c3;
            unpack2(acc[i][0], c0, c1);
            unpack2(acc[i][1], c2, c3);
            c0 += b4[0]; c1 += b4[1]; c2 += b4[2]; c3 += b4[3];
            if (relu) {
                c0 = fmaxf(c0, 0.f); c1 = fmaxf(c1, 0.f);
                c2 = fmaxf(c2, 0.f); c3 = fmaxf(c3, 0.f);
            }
            *(float4*)(C + (size_t)m * ldc + n0 + tx * 4) = make_float4(c0, c1, c2, c3);
        }
    }
}

__global__ void k_concat(const float* __restrict__ hs, const float* __restrict__ hm,
                         const float* __restrict__ hl) {
    int i = blockIdx.x * 256 + threadIdx.x;
    if (i >= NN * H3) return;
    int n = i / H3, j = i % H3;
    float v;
    if (j < 256)      v = hs[n * HD + j];
    else if (j < 512) v = hm[n * HD + j - 256];
    else              v = hl[n * HD + j - 512];
    d_COMB[i] = v;
}

// ---------------- SAGE attention (decomposed scores) ----------------
__device__ __forceinline__ unsigned fenc(float f) {
    unsigned u = __float_as_uint(f);
    return (u & 0x80000000u) ? ~u : (u | 0x80000000u);
}
__device__ __forceinline__ float fdec(unsigned u) {
    u = (u & 0x80000000u) ? (u & 0x7fffffffu) : ~u;
    return __uint_as_float(u);
}

__global__ void k_pq(const float* __restrict__ aw) {
    int n = blockIdx.x * 8 + (threadIdx.x >> 5);
    int lane = threadIdx.x & 31;
    if (n >= NN) return;
    float p = 0.f, q = 0.f;
#pragma unroll
    for (int j = lane; j < 256; j += 32) {
        float v = d_XL[n * GD + j];
        p += v * aw[j];
        q += v * aw[256 + j];
    }
#pragma unroll
    for (int o = 16; o; o >>= 1) {
        p += __shfl_xor_sync(0xffffffffu, p, o);
        q += __shfl_xor_sync(0xffffffffu, q, o);
    }
    if (lane == 0) { d_P[n] = p; d_Q[n] = q; }
}

__global__ void k_init() {
    int n = blockIdx.x * 256 + threadIdx.x;
    if (n < NN) { d_MENC[n] = 0x007fffffu; d_SSUM[n] = 0.f; }
}

__global__ void k_edge1(const int* __restrict__ ei, const float* __restrict__ ea,
                        const float* __restrict__ aw, const float* __restrict__ ab) {
    int e = blockIdx.x * 256 + threadIdx.x;
    if (e >= NE) return;
    int row = ei[e], col = ei[NE + e];
    float sc = d_P[row] + d_Q[col] + aw[512] * ea[e] + ab[0];
    d_SC[e] = sc;
    atomicMax(&d_MENC[row], fenc(sc));
}

__global__ void k_edge2(const int* __restrict__ ei) {
    int e = blockIdx.x * 256 + threadIdx.x;
    if (e >= NE) return;
    int row = ei[e];
    float m = fdec(d_MENC[row]);
    float ex = expf(d_SC[e] - m);
    d_SC[e] = ex;
    atomicAdd(&d_SSUM[row], ex);
}

__global__ void k_edge3(const int* __restrict__ ei) {
    int e = blockIdx.x * 4 + (threadIdx.x >> 6);
    int l = threadIdx.x & 63;
    if (e >= NE) return;
    int row = ei[e], col = ei[NE + e];
    float alpha = d_SC[e] / (d_SSUM[row] + 1e-16f);
    float4 v = *(const float4*)&d_XL[row * GD + l * 4];
    float* dst = &d_AGG[col * GD + l * 4];
    atomicAdd(dst + 0, alpha * v.x);
    atomicAdd(dst + 1, alpha * v.y);
    atomicAdd(dst + 2, alpha * v.z);
    atomicAdd(dst + 3, alpha * v.w);
}

__global__ void k_finish(const float* __restrict__ addsrc, float* __restrict__ dst) {
    int i = blockIdx.x * 256 + threadIdx.x;
    if (i >= NN * GD) return;
    float v = d_AGG[i];
    v = v > 0.f ? v : 0.f;
    if (addsrc) v += addsrc[i];
    dst[i] = v;
}

__global__ void k_heads(const float* __restrict__ impW, const float* __restrict__ impb,
                        const float* __restrict__ uncW, const float* __restrict__ uncb,
                        float* __restrict__ out) {
    int n = blockIdx.x * 8 + (threadIdx.x >> 5);
    int lane = threadIdx.x & 31;
    if (n >= NN) return;
    float a = 0.f, b = 0.f;
#pragma unroll
    for (int j = lane; j < GD; j += 32) {
        float v = d_G2[n * GD + j];
        a += v * impW[j];
        b += v * uncW[j];
    }
#pragma unroll
    for (int o = 16; o; o >>= 1) {
        a += __shfl_xor_sync(0xffffffffu, a, o);
        b += __shfl_xor_sync(0xffffffffu, b, o);
    }
    if (lane == 0) {
        out[n] = tanhf(a + impb[0]);
        out[NN + n] = 1.f / (1.f + expf(-(b + uncb[0])));
    }
}

// ---------------- host orchestration ----------------
extern "C" void kernel_launch(void* const* d_in, const int* in_sizes, int n_in,
                              void* d_out, int out_size)
{
    const float* x_s = (const float*)d_in[0];
    const float* x_m = (const float*)d_in[1];
    const float* x_l = (const float*)d_in[2];
    const int*   ei  = (const int*)d_in[3];
    const float* ea  = (const float*)d_in[4];
    const float* Wih[3] = {(const float*)d_in[5], (const float*)d_in[9],  (const float*)d_in[13]};
    const float* Whh[3] = {(const float*)d_in[6], (const float*)d_in[10], (const float*)d_in[14]};
    const float* bih[3] = {(const float*)d_in[7], (const float*)d_in[11], (const float*)d_in[15]};
    const float* bhh[3] = {(const float*)d_in[8], (const float*)d_in[12], (const float*)d_in[16]};
    const float* fW   = (const float*)d_in[17];
    const float* fb   = (const float*)d_in[18];
    const float* g1W  = (const float*)d_in[19];
    const float* g1aw = (const float*)d_in[20];
    const float* g1ab = (const float*)d_in[21];
    const float* g2W  = (const float*)d_in[22];
    const float* g2aw = (const float*)d_in[23];
    const float* g2ab = (const float*)d_in[24];
    const float* impW = (const float*)d_in[25];
    const float* impb = (const float*)d_in[26];
    const float* uncW = (const float*)d_in[27];
    const float* uncb = (const float*)d_in[28];

    void *pCOMB, *pHS, *pHM, *pHL, *pHT, *pTEMB, *pXL, *pAGG, *pG1, *pG2;
    cudaGetSymbolAddress(&pCOMB, d_COMB);
    cudaGetSymbolAddress(&pHS, d_HS);
    cudaGetSymbolAddress(&pHM, d_HM);
    cudaGetSymbolAddress(&pHL, d_HL);
    cudaGetSymbolAddress(&pHT, d_HT);
    cudaGetSymbolAddress(&pTEMB, d_TEMB);
    cudaGetSymbolAddress(&pXL, d_XL);
    cudaGetSymbolAddress(&pAGG, d_AGG);
    cudaGetSymbolAddress(&pG1, d_G1);
    cudaGetSymbolAddress(&pG2, d_G2);
    float* COMB = (float*)pCOMB;
    float* HS = (float*)pHS; float* HM = (float*)pHM; float* HL = (float*)pHL;
    float* HT = (float*)pHT;
    float* TEMB = (float*)pTEMB; float* XL = (float*)pXL; float* AGG = (float*)pAGG;
    float* G1 = (float*)pG1;   float* G2 = (float*)pG2;

    cudaFuncSetAttribute(fused_gru_step,
                         cudaFuncAttributeMaxDynamicSharedMemorySize, FUSED_SMEM);

    const float* xs[3] = {x_s, x_m, x_l};
    const int Ts[3] = {8, 30, 60};
    float* hfin[3] = {HS, HM, HL};

    dim3 gF(79, 4);   // fused GRU step: M=10000/128, 4 col groups
    dim3 gS((NN + 127) / 128, GD / 64);

    // ---- three GRUs (T even => final h lands in hfin[s]) ----
    for (int s = 0; s < 3; s++) {
        cudaMemsetAsync(hfin[s], 0, (size_t)NN * HD * sizeof(float));
        for (int t = 0; t < Ts[s]; t++) {
            float* hin  = (t & 1) ? HT : hfin[s];
            float* hout = (t & 1) ? hfin[s] : HT;
            fused_gru_step<<<gF, 512, FUSED_SMEM>>>(
                xs[s] + (size_t)t * FD, Ts[s] * FD, hin, hout,
                Wih[s], Whh[s], bih[s], bhh[s]);
        }
    }

    // ---- fusion ----
    k_concat<<<(NN * H3 + 255) / 256, 256>>>(HS, HM, HL);
    gemm_tn<<<gS, 256>>>(COMB, H3, fW, H3, fb, TEMB, GD, NN, H3, 1);

    // ---- SAGE layer 1 ----
    gemm_tn<<<gS, 256>>>(TEMB, GD, g1W, GD, nullptr, XL, GD, NN, GD, 0);
    k_pq<<<(NN + 7) / 8, 256>>>(g1aw);
    k_init<<<(NN + 255) / 256, 256>>>();
    cudaMemsetAsync(AGG, 0, (size_t)NN * GD * sizeof(float));
    k_edge1<<<(NE + 255) / 256, 256>>>(ei, ea, g1aw, g1ab);
    k_edge2<<<(NE + 255) / 256, 256>>>(ei);
    k_edge3<<<NE / 4, 256>>>(ei);
    k_finish<<<(NN * GD + 255) / 256, 256>>>(nullptr, G1);

    // ---- SAGE layer 2 ----
    gemm_tn<<<gS, 256>>>(G1, GD, g2W, GD, nullptr, XL, GD, NN, GD, 0);
    k_pq<<<(NN + 7) / 8, 256>>>(g2aw);
    k_init<<<(NN + 255) / 256, 256>>>();
    cudaMemsetAsync(AGG, 0, (size_t)NN * GD * sizeof(float));
    k_edge1<<<(NE + 255) / 256, 256>>>(ei, ea, g2aw, g2ab);
    k_edge2<<<(NE + 255) / 256, 256>>>(ei);
    k_edge3<<<NE / 4, 256>>>(ei);
    k_finish<<<(NN * GD + 255) / 256, 256>>>(TEMB, G2);

    // ---- heads ----
    k_heads<<<(NN + 7) / 8, 256>>>(impW, impb, uncW, uncb, (float*)d_out);
}